// round 8
// baseline (speedup 1.0000x reference)
#include <cuda_runtime.h>
#include <cuda_fp16.h>
#include <mma.h>
#include <cstdint>

using namespace nvcuda;

#define N_CELLS 8192
#define D_GENE  1024
#define D_EMB   256
#define KCAT    768   // [hi | lo | hi] split concat along K

// ---------------- scratch (device globals; no allocation allowed) ----------------
__device__ __half g_Bcat[(size_t)N_CELLS * KCAT];   // [Eh | Eh | El]   [N,K]
__device__ __half g_Acat[(size_t)N_CELLS * KCAT];   // [Ph | Pl | Ph]   [M,K]
__device__ __half g_B2[(size_t)KCAT * D_EMB];       // [Th ; Tl ; Th]   [K,N]
__device__ __half g_Xh[(size_t)N_CELLS * D_GENE];   // expression fp16  [K,N]
__device__ __half g_Gh[(size_t)D_GENE * D_GENE];    // gene_response    [K,N]
__device__ __half g_gated[(size_t)N_CELLS * N_CELLS]; // gated matrix   128 MB
__device__ __half g_M1h[(size_t)N_CELLS * D_GENE];  // (gated@expr)

// ---------------- conversion kernels (R1 originals, proven) ----------------
__global__ void k_cvt_expr(const float* __restrict__ in) {
    int i = blockIdx.x * blockDim.x + threadIdx.x;
    if (i < N_CELLS * D_GENE) g_Xh[i] = __float2half_rn(in[i]);
}

__global__ void k_cvt_gr(const float* __restrict__ in) {
    int i = blockIdx.x * blockDim.x + threadIdx.x;
    if (i < D_GENE * D_GENE) g_Gh[i] = __float2half_rn(in[i]);
}

__global__ void k_cvt_enc(const float* __restrict__ enc) {
    int i = blockIdx.x * blockDim.x + threadIdx.x;
    if (i >= N_CELLS * D_EMB) return;
    int m = i / D_EMB, c = i % D_EMB;
    float x = enc[i];
    __half h = __float2half_rn(x);
    __half l = __float2half_rn(x - __half2float(h));
    size_t base = (size_t)m * KCAT + c;
    g_Bcat[base]             = h;
    g_Bcat[base + D_EMB]     = h;
    g_Bcat[base + 2 * D_EMB] = l;
}

__global__ void k_cvt_T(const float* __restrict__ T) {
    int i = blockIdx.x * blockDim.x + threadIdx.x;
    if (i >= D_EMB * D_EMB) return;
    int k = i / D_EMB, j = i % D_EMB;
    float x = T[i];
    __half h = __float2half_rn(x);
    __half l = __float2half_rn(x - __half2float(h));
    g_B2[(size_t)k * D_EMB + j]               = h;
    g_B2[(size_t)(k + D_EMB) * D_EMB + j]     = l;
    g_B2[(size_t)(k + 2 * D_EMB) * D_EMB + j] = h;
}

// ---------------- wmma GEMM: CTA 128x256, warp tile 64x64, k-chunk 16 ------------
// Software pipeline: two register staging sets, fetch distance 2.
//   iter it:  STS(it) -> sync -> LDG(it+2) -> compute(it)
// MODE 0: P   = Bcat @ B2        (M=8192, N=256,  K=768)   B row-major [K,N]
// MODE 1: S   = Acat @ Bcat^T    (M=8192, N=8192, K=768)   B col-major [N,K]
// MODE 2: M1  = gated @ Xh       (M=8192, N=1024, K=8192)  B row-major [K,N]
// MODE 3: out = M1h @ Gh         (M=8192, N=1024, K=1024)  B row-major [K,N]
template <int MODE>
__global__ __launch_bounds__(256)
void gemm_wmma4(const float* __restrict__ aux, float* __restrict__ outf) {
    constexpr bool B_COL = (MODE == 1);
    constexpr int K    = (MODE <= 1) ? KCAT : (MODE == 2 ? N_CELLS : D_GENE);
    constexpr int NK   = K / 16;
    constexpr int Ndim = (MODE == 0) ? D_EMB : (MODE == 1 ? N_CELLS : D_GENE);
    constexpr int LDA  = 24;    // A smem pitch (halves)

    const __half* __restrict__ A =
        (MODE == 0) ? g_Bcat : (MODE == 1) ? g_Acat : (MODE == 2) ? g_gated : g_M1h;
    const __half* __restrict__ B =
        (MODE == 0) ? g_B2 : (MODE == 1) ? g_Bcat : (MODE == 2) ? g_Xh : g_Gh;

    __shared__ __align__(16) __half As[2][128 * 24];   // 12288 B
    __shared__ __align__(16) __half Bs[2][6144];       // 24576 B (col: 256x24; row: 16x264)
    __shared__ __align__(16) float  epbuf[8][320];     // 10240 B  => total 47104 B

    const int tid  = threadIdx.x;
    const int lane = tid & 31;
    const int w    = tid >> 5;
    const int wm   = w >> 2;   // 0..1
    const int wn   = w & 3;    // 0..3
    const size_t gm0 = (size_t)blockIdx.y * 128;
    const size_t gn0 = (size_t)blockIdx.x * 256;

    wmma::fragment<wmma::accumulator, 16, 16, 16, float> acc[4][4];
#pragma unroll
    for (int i = 0; i < 4; i++)
#pragma unroll
        for (int j = 0; j < 4; j++) wmma::fill_fragment(acc[i][j], 0.0f);

    // ---- two register staging sets (fetch distance 2) ----
    float4 rA[2], rB[2][2];
    const int arow = tid >> 1, ach = tid & 1;          // A: 128 rows x 2 chunks

    auto fetch = [&](int k0, int s) {
        rA[s] = *(const float4*)(A + (gm0 + arow) * (size_t)K + k0 + ach * 8);
        if (B_COL) {
#pragma unroll
            for (int j = 0; j < 2; j++) {
                int idx = tid + j * 256;
                int row = idx >> 1, ch = idx & 1;      // 256 rows x 2 chunks
                rB[s][j] = *(const float4*)(B + (gn0 + row) * (size_t)K + k0 + ch * 8);
            }
        } else {
#pragma unroll
            for (int j = 0; j < 2; j++) {
                int idx = tid + j * 256;
                int row = idx >> 5, ch = idx & 31;     // 16 rows x 32 chunks
                rB[s][j] = *(const float4*)(B + (size_t)(k0 + row) * Ndim + gn0 + ch * 8);
            }
        }
    };
    auto store = [&](int buf, int s) {
        *(float4*)(&As[buf][arow * LDA + ach * 8]) = rA[s];
        if (B_COL) {
#pragma unroll
            for (int j = 0; j < 2; j++) {
                int idx = tid + j * 256;
                int row = idx >> 1, ch = idx & 1;
                *(float4*)(&Bs[buf][row * 24 + ch * 8]) = rB[s][j];
            }
        } else {
#pragma unroll
            for (int j = 0; j < 2; j++) {
                int idx = tid + j * 256;
                int row = idx >> 5, ch = idx & 31;
                *(float4*)(&Bs[buf][row * 264 + ch * 8]) = rB[s][j];
            }
        }
    };

    fetch(0, 0);
    fetch(16, 1);

#pragma unroll 1
    for (int it = 0; it < NK; ++it) {
        const int buf = it & 1;
        store(buf, buf);
        __syncthreads();   // stage visible; C(it-2) on this buf finished before sync(it-1)
        if (it + 2 < NK) fetch((it + 2) * 16, buf);   // 2 compute phases to land

        if constexpr (B_COL) {
            wmma::fragment<wmma::matrix_b, 16, 16, 16, __half, wmma::col_major> b[4];
#pragma unroll
            for (int nt = 0; nt < 4; nt++)
                wmma::load_matrix_sync(b[nt], &Bs[buf][(wn * 64 + nt * 16) * 24], 24);
#pragma unroll
            for (int mt = 0; mt < 4; mt++) {
                wmma::fragment<wmma::matrix_a, 16, 16, 16, __half, wmma::row_major> a;
                wmma::load_matrix_sync(a, &As[buf][(wm * 64 + mt * 16) * LDA], LDA);
#pragma unroll
                for (int nt = 0; nt < 4; nt++)
                    wmma::mma_sync(acc[mt][nt], a, b[nt], acc[mt][nt]);
            }
        } else {
            wmma::fragment<wmma::matrix_b, 16, 16, 16, __half, wmma::row_major> b[4];
#pragma unroll
            for (int nt = 0; nt < 4; nt++)
                wmma::load_matrix_sync(b[nt], &Bs[buf][wn * 64 + nt * 16], 264);
#pragma unroll
            for (int mt = 0; mt < 4; mt++) {
                wmma::fragment<wmma::matrix_a, 16, 16, 16, __half, wmma::row_major> a;
                wmma::load_matrix_sync(a, &As[buf][(wm * 64 + mt * 16) * LDA], LDA);
#pragma unroll
                for (int nt = 0; nt < 4; nt++)
                    wmma::mma_sync(acc[mt][nt], a, b[nt], acc[mt][nt]);
            }
        }
    }

    // ---------------- epilogue (per-warp staging, proven pattern) ----------------
    const int r  = lane >> 1;
    const int cb = (lane & 1) * 8;
#pragma unroll
    for (int mt = 0; mt < 4; mt++) {
        const size_t gr = gm0 + wm * 64 + mt * 16 + r;
#pragma unroll
        for (int nt = 0; nt < 4; nt++) {
            wmma::store_matrix_sync(&epbuf[w][0], acc[mt][nt], 20, wmma::mem_row_major);
            __syncwarp();
            const size_t gc = gn0 + wn * 64 + nt * 16 + cb;
            float v[8];
#pragma unroll
            for (int e = 0; e < 8; e++) v[e] = epbuf[w][r * 20 + cb + e];

            if constexpr (MODE == 0) {
                __half2 hh[4], ll[4];
#pragma unroll
                for (int e = 0; e < 4; e++) {
                    __half h0 = __float2half_rn(v[e * 2]);
                    __half h1 = __float2half_rn(v[e * 2 + 1]);
                    hh[e] = __halves2half2(h0, h1);
                    ll[e] = __halves2half2(
                        __float2half_rn(v[e * 2]     - __half2float(h0)),
                        __float2half_rn(v[e * 2 + 1] - __half2float(h1)));
                }
                size_t base = gr * KCAT + gc;
                *(uint4*)(g_Acat + base)             = *(uint4*)hh;
                *(uint4*)(g_Acat + base + D_EMB)     = *(uint4*)ll;
                *(uint4*)(g_Acat + base + 2 * D_EMB) = *(uint4*)hh;
            } else if constexpr (MODE == 1) {
                const float* prow = aux + gr * (size_t)N_CELLS + gc;
                float4 p0 = __ldcs((const float4*)prow);
                float4 p1 = __ldcs((const float4*)(prow + 4));
                float pv[8] = {p0.x, p0.y, p0.z, p0.w, p1.x, p1.y, p1.z, p1.w};
                __half2 o[4];
#pragma unroll
                for (int e = 0; e < 4; e++) {
                    float s0 = __expf(pv[e * 2]     * -1e-4f) / (1.0f + __expf(-v[e * 2]));
                    float s1 = __expf(pv[e * 2 + 1] * -1e-4f) / (1.0f + __expf(-v[e * 2 + 1]));
                    o[e] = __floats2half2_rn(s0, s1);
                }
                *(uint4*)(g_gated + gr * (size_t)N_CELLS + gc) = *(uint4*)o;
            } else if constexpr (MODE == 2) {
                __half2 o[4];
#pragma unroll
                for (int e = 0; e < 4; e++)
                    o[e] = __floats2half2_rn(v[e * 2], v[e * 2 + 1]);
                *(uint4*)(g_M1h + gr * D_GENE + gc) = *(uint4*)o;
            } else {
                float4 o0 = make_float4(v[0] * (1.0f / 1024.0f), v[1] * (1.0f / 1024.0f),
                                        v[2] * (1.0f / 1024.0f), v[3] * (1.0f / 1024.0f));
                float4 o1 = make_float4(v[4] * (1.0f / 1024.0f), v[5] * (1.0f / 1024.0f),
                                        v[6] * (1.0f / 1024.0f), v[7] * (1.0f / 1024.0f));
                *(float4*)(outf + gr * D_GENE + gc)     = o0;
                *(float4*)(outf + gr * D_GENE + gc + 4) = o1;
            }
            __syncwarp();
        }
    }
}

// ---------------- launch ----------------
extern "C" void kernel_launch(void* const* d_in, const int* in_sizes, int n_in,
                              void* d_out, int out_size) {
    const float* expr = (const float*)d_in[0];
    const float* enc  = (const float*)d_in[1];
    const float* pd   = (const float*)d_in[2];
    const float* T    = (const float*)d_in[3];
    const float* gr   = (const float*)d_in[4];
    float* out = (float*)d_out;

    // conversions (R1 originals)
    k_cvt_expr<<<(N_CELLS * D_GENE) / 256, 256>>>(expr);
    k_cvt_gr<<<(D_GENE * D_GENE) / 256, 256>>>(gr);
    k_cvt_enc<<<(N_CELLS * D_EMB) / 256, 256>>>(enc);
    k_cvt_T<<<(D_EMB * D_EMB) / 256, 256>>>(T);

    // GEMM chain (CTA 128x256; grid.x fastest for L2 reuse of A panels)
    gemm_wmma4<0><<<dim3(D_EMB / 256,  N_CELLS / 128), 256>>>(nullptr, nullptr);
    gemm_wmma4<1><<<dim3(N_CELLS / 256, N_CELLS / 128), 256>>>(pd, nullptr);
    gemm_wmma4<2><<<dim3(D_GENE / 256, N_CELLS / 128), 256>>>(nullptr, nullptr);
    gemm_wmma4<3><<<dim3(D_GENE / 256, N_CELLS / 128), 256>>>(nullptr, out);
}

// round 9
// speedup vs baseline: 1.3889x; 1.3889x over previous
#include <cuda_runtime.h>
#include <cuda_fp16.h>
#include <mma.h>
#include <cstdint>

using namespace nvcuda;

#define N_CELLS 8192
#define D_GENE  1024
#define D_EMB   256
#define KCAT    768   // [hi | lo | hi] split concat along K

// ---------------- scratch (device globals; no allocation allowed) ----------------
__device__ __half g_Bcat[(size_t)N_CELLS * KCAT];   // [Eh | Eh | El]   [N,K]
__device__ __half g_Acat[(size_t)N_CELLS * KCAT];   // [Ph | Pl | Ph]   [M,K]
__device__ __half g_B2[(size_t)KCAT * D_EMB];       // [Th ; Tl ; Th]   [K,N]
__device__ __half g_Xh[(size_t)N_CELLS * D_GENE];   // expression fp16  [K,N]
__device__ __half g_Gh[(size_t)D_GENE * D_GENE];    // gene_response    [K,N]
__device__ __half g_gated[(size_t)N_CELLS * N_CELLS]; // gated matrix   128 MB
__device__ __half g_M1h[(size_t)N_CELLS * D_GENE];  // (gated@expr)

// ---------------- conversion kernels (R1 originals, proven) ----------------
__global__ void k_cvt_expr(const float* __restrict__ in) {
    int i = blockIdx.x * blockDim.x + threadIdx.x;
    if (i < N_CELLS * D_GENE) g_Xh[i] = __float2half_rn(in[i]);
}

__global__ void k_cvt_gr(const float* __restrict__ in) {
    int i = blockIdx.x * blockDim.x + threadIdx.x;
    if (i < D_GENE * D_GENE) g_Gh[i] = __float2half_rn(in[i]);
}

__global__ void k_cvt_enc(const float* __restrict__ enc) {
    int i = blockIdx.x * blockDim.x + threadIdx.x;
    if (i >= N_CELLS * D_EMB) return;
    int m = i / D_EMB, c = i % D_EMB;
    float x = enc[i];
    __half h = __float2half_rn(x);
    __half l = __float2half_rn(x - __half2float(h));
    size_t base = (size_t)m * KCAT + c;
    g_Bcat[base]             = h;
    g_Bcat[base + D_EMB]     = h;
    g_Bcat[base + 2 * D_EMB] = l;
}

__global__ void k_cvt_T(const float* __restrict__ T) {
    int i = blockIdx.x * blockDim.x + threadIdx.x;
    if (i >= D_EMB * D_EMB) return;
    int k = i / D_EMB, j = i % D_EMB;
    float x = T[i];
    __half h = __float2half_rn(x);
    __half l = __float2half_rn(x - __half2float(h));
    g_B2[(size_t)k * D_EMB + j]               = h;
    g_B2[(size_t)(k + D_EMB) * D_EMB + j]     = l;
    g_B2[(size_t)(k + 2 * D_EMB) * D_EMB + j] = h;
}

// ---------------- wmma GEMM: CTA 128x128 (4 warps), warp tile 64x64, k-chunk 32 --
// R1-proven serial structure (LDG->STS, sync, compute, sync). No staging registers.
// 2 CTAs/SM co-residency does the latency hiding.
// MODE 0: P   = Bcat @ B2        (M=8192, N=256,  K=768)   B row-major [K,N]
// MODE 1: S   = Acat @ Bcat^T    (M=8192, N=8192, K=768)   B col-major [N,K]
// MODE 2: M1  = gated @ Xh       (M=8192, N=1024, K=8192)  B row-major [K,N]
// MODE 3: out = M1h @ Gh         (M=8192, N=1024, K=1024)  B row-major [K,N]
template <int MODE>
__global__ void gemm_wmma5(const float* __restrict__ aux, float* __restrict__ outf) {
    constexpr bool B_COL = (MODE == 1);
    constexpr int K    = (MODE <= 1) ? KCAT : (MODE == 2 ? N_CELLS : D_GENE);
    constexpr int Ndim = (MODE == 0) ? D_EMB : (MODE == 1 ? N_CELLS : D_GENE);
    constexpr int LDA  = 40;                  // A pitch (halves): 32 data + 8 pad
    constexpr int LDB  = B_COL ? 40 : 136;    // B pitch: [n][k] 40 | [k][n] 128+8

    const __half* __restrict__ A =
        (MODE == 0) ? g_Bcat : (MODE == 1) ? g_Acat : (MODE == 2) ? g_gated : g_M1h;
    const __half* __restrict__ B =
        (MODE == 0) ? g_B2 : (MODE == 1) ? g_Bcat : (MODE == 2) ? g_Xh : g_Gh;

    __shared__ __align__(16) __half As[128 * 40];   // 10240 B
    __shared__ __align__(16) __half Bs[5120];       // 10240 B (col: 128x40; row: 32x136=4352)
    __shared__ __align__(16) float  epbuf[4][320];  // 5120 B   => 25600 B/CTA

    const int tid  = threadIdx.x;    // 0..127
    const int lane = tid & 31;
    const int w    = tid >> 5;       // 0..3
    const int wm   = w >> 1;         // 0..1 -> m offset wm*64
    const int wn   = w & 1;          // 0..1 -> n offset wn*64
    const size_t gm0 = (size_t)blockIdx.y * 128;
    const size_t gn0 = (size_t)blockIdx.x * 128;

    wmma::fragment<wmma::accumulator, 16, 16, 16, float> acc[4][4];
#pragma unroll
    for (int i = 0; i < 4; i++)
#pragma unroll
        for (int j = 0; j < 4; j++) wmma::fill_fragment(acc[i][j], 0.0f);

#pragma unroll 1
    for (int k0 = 0; k0 < K; k0 += 32) {
        // ---- serial load: A 8KB + B 8KB, 4 float4 each per thread ----
#pragma unroll
        for (int j = 0; j < 4; j++) {
            int idx = tid + j * 128;
            int row = idx >> 2, ch = idx & 3;    // 128 rows x 4 chunks(16B)
            *(float4*)(&As[row * LDA + ch * 8]) =
                *(const float4*)(A + (gm0 + row) * (size_t)K + k0 + ch * 8);
        }
        if (B_COL) {
#pragma unroll
            for (int j = 0; j < 4; j++) {
                int idx = tid + j * 128;
                int row = idx >> 2, ch = idx & 3;
                *(float4*)(&Bs[row * 40 + ch * 8]) =
                    *(const float4*)(B + (gn0 + row) * (size_t)K + k0 + ch * 8);
            }
        } else {
#pragma unroll
            for (int j = 0; j < 4; j++) {
                int idx = tid + j * 128;
                int row = idx >> 4, ch = idx & 15;   // 32 rows x 16 chunks
                *(float4*)(&Bs[row * 136 + ch * 8]) =
                    *(const float4*)(B + (size_t)(k0 + row) * Ndim + gn0 + ch * 8);
            }
        }
        __syncthreads();

#pragma unroll
        for (int kk = 0; kk < 32; kk += 16) {
            if constexpr (B_COL) {
                wmma::fragment<wmma::matrix_b, 16, 16, 16, __half, wmma::col_major> b[4];
#pragma unroll
                for (int nt = 0; nt < 4; nt++)
                    wmma::load_matrix_sync(b[nt], &Bs[(wn * 64 + nt * 16) * 40 + kk], 40);
#pragma unroll
                for (int mt = 0; mt < 4; mt++) {
                    wmma::fragment<wmma::matrix_a, 16, 16, 16, __half, wmma::row_major> a;
                    wmma::load_matrix_sync(a, &As[(wm * 64 + mt * 16) * LDA + kk], LDA);
#pragma unroll
                    for (int nt = 0; nt < 4; nt++)
                        wmma::mma_sync(acc[mt][nt], a, b[nt], acc[mt][nt]);
                }
            } else {
                wmma::fragment<wmma::matrix_b, 16, 16, 16, __half, wmma::row_major> b[4];
#pragma unroll
                for (int nt = 0; nt < 4; nt++)
                    wmma::load_matrix_sync(b[nt], &Bs[kk * 136 + wn * 64 + nt * 16], 136);
#pragma unroll
                for (int mt = 0; mt < 4; mt++) {
                    wmma::fragment<wmma::matrix_a, 16, 16, 16, __half, wmma::row_major> a;
                    wmma::load_matrix_sync(a, &As[(wm * 64 + mt * 16) * LDA + kk], LDA);
#pragma unroll
                    for (int nt = 0; nt < 4; nt++)
                        wmma::mma_sync(acc[mt][nt], a, b[nt], acc[mt][nt]);
                }
            }
        }
        __syncthreads();
    }

    // ---------------- epilogue (per-warp staging, proven pattern) ----------------
    const int r  = lane >> 1;
    const int cb = (lane & 1) * 8;
#pragma unroll
    for (int mt = 0; mt < 4; mt++) {
        const size_t gr = gm0 + wm * 64 + mt * 16 + r;
#pragma unroll
        for (int nt = 0; nt < 4; nt++) {
            wmma::store_matrix_sync(&epbuf[w][0], acc[mt][nt], 20, wmma::mem_row_major);
            __syncwarp();
            const size_t gc = gn0 + wn * 64 + nt * 16 + cb;
            float v[8];
#pragma unroll
            for (int e = 0; e < 8; e++) v[e] = epbuf[w][r * 20 + cb + e];

            if constexpr (MODE == 0) {
                __half2 hh[4], ll[4];
#pragma unroll
                for (int e = 0; e < 4; e++) {
                    __half h0 = __float2half_rn(v[e * 2]);
                    __half h1 = __float2half_rn(v[e * 2 + 1]);
                    hh[e] = __halves2half2(h0, h1);
                    ll[e] = __halves2half2(
                        __float2half_rn(v[e * 2]     - __half2float(h0)),
                        __float2half_rn(v[e * 2 + 1] - __half2float(h1)));
                }
                size_t base = gr * KCAT + gc;
                *(uint4*)(g_Acat + base)             = *(uint4*)hh;
                *(uint4*)(g_Acat + base + D_EMB)     = *(uint4*)ll;
                *(uint4*)(g_Acat + base + 2 * D_EMB) = *(uint4*)hh;
            } else if constexpr (MODE == 1) {
                const float* prow = aux + gr * (size_t)N_CELLS + gc;
                float4 p0 = __ldcs((const float4*)prow);
                float4 p1 = __ldcs((const float4*)(prow + 4));
                float pv[8] = {p0.x, p0.y, p0.z, p0.w, p1.x, p1.y, p1.z, p1.w};
                __half2 o[4];
#pragma unroll
                for (int e = 0; e < 4; e++) {
                    float s0 = __expf(pv[e * 2]     * -1e-4f) / (1.0f + __expf(-v[e * 2]));
                    float s1 = __expf(pv[e * 2 + 1] * -1e-4f) / (1.0f + __expf(-v[e * 2 + 1]));
                    o[e] = __floats2half2_rn(s0, s1);
                }
                *(uint4*)(g_gated + gr * (size_t)N_CELLS + gc) = *(uint4*)o;
            } else if constexpr (MODE == 2) {
                __half2 o[4];
#pragma unroll
                for (int e = 0; e < 4; e++)
                    o[e] = __floats2half2_rn(v[e * 2], v[e * 2 + 1]);
                *(uint4*)(g_M1h + gr * D_GENE + gc) = *(uint4*)o;
            } else {
                float4 o0 = make_float4(v[0] * (1.0f / 1024.0f), v[1] * (1.0f / 1024.0f),
                                        v[2] * (1.0f / 1024.0f), v[3] * (1.0f / 1024.0f));
                float4 o1 = make_float4(v[4] * (1.0f / 1024.0f), v[5] * (1.0f / 1024.0f),
                                        v[6] * (1.0f / 1024.0f), v[7] * (1.0f / 1024.0f));
                *(float4*)(outf + gr * D_GENE + gc)     = o0;
                *(float4*)(outf + gr * D_GENE + gc + 4) = o1;
            }
            __syncwarp();
        }
    }
}

// ---------------- launch ----------------
extern "C" void kernel_launch(void* const* d_in, const int* in_sizes, int n_in,
                              void* d_out, int out_size) {
    const float* expr = (const float*)d_in[0];
    const float* enc  = (const float*)d_in[1];
    const float* pd   = (const float*)d_in[2];
    const float* T    = (const float*)d_in[3];
    const float* gr   = (const float*)d_in[4];
    float* out = (float*)d_out;

    // Order chosen so the 4th launch (ncu capture slot) is the dominant GEMM1.
    k_cvt_enc<<<(N_CELLS * D_EMB) / 256, 256>>>(enc);
    k_cvt_T<<<(D_EMB * D_EMB) / 256, 256>>>(T);
    gemm_wmma5<0><<<dim3(D_EMB / 128,  N_CELLS / 128), 128>>>(nullptr, nullptr);
    gemm_wmma5<1><<<dim3(N_CELLS / 128, N_CELLS / 128), 128>>>(pd, nullptr);
    k_cvt_expr<<<(N_CELLS * D_GENE) / 256, 256>>>(expr);
    k_cvt_gr<<<(D_GENE * D_GENE) / 256, 256>>>(gr);
    gemm_wmma5<2><<<dim3(D_GENE / 128, N_CELLS / 128), 128>>>(nullptr, nullptr);
    gemm_wmma5<3><<<dim3(D_GENE / 128, N_CELLS / 128), 128>>>(nullptr, out);
}

// round 10
// speedup vs baseline: 1.5582x; 1.1219x over previous
#include <cuda_runtime.h>
#include <cuda_fp16.h>
#include <mma.h>
#include <cstdint>

using namespace nvcuda;

#define N_CELLS 8192
#define D_GENE  1024
#define D_EMB   256
#define KCAT    768   // [hi | lo | hi] split concat along K

// ---------------- scratch (device globals; no allocation allowed) ----------------
__device__ __half g_Bcat[(size_t)N_CELLS * KCAT];   // [Eh | Eh | El]   [N,K]
__device__ __half g_Acat[(size_t)N_CELLS * KCAT];   // [Ph | Pl | Ph]   [M,K]
__device__ __half g_B2[(size_t)KCAT * D_EMB];       // [Th ; Tl ; Th]   [K,N]
__device__ __half g_Xh[(size_t)N_CELLS * D_GENE];   // expression fp16  [K,N]
__device__ __half g_Gh[(size_t)D_GENE * D_GENE];    // gene_response    [K,N]
__device__ __half g_gated[(size_t)N_CELLS * N_CELLS]; // gated matrix   128 MB
__device__ __half g_M1h[(size_t)N_CELLS * D_GENE];  // (gated@expr)

// ---------------- conversion kernels (R1 originals, proven) ----------------
__global__ void k_cvt_expr(const float* __restrict__ in) {
    int i = blockIdx.x * blockDim.x + threadIdx.x;
    if (i < N_CELLS * D_GENE) g_Xh[i] = __float2half_rn(in[i]);
}

__global__ void k_cvt_gr(const float* __restrict__ in) {
    int i = blockIdx.x * blockDim.x + threadIdx.x;
    if (i < D_GENE * D_GENE) g_Gh[i] = __float2half_rn(in[i]);
}

__global__ void k_cvt_enc(const float* __restrict__ enc) {
    int i = blockIdx.x * blockDim.x + threadIdx.x;
    if (i >= N_CELLS * D_EMB) return;
    int m = i / D_EMB, c = i % D_EMB;
    float x = enc[i];
    __half h = __float2half_rn(x);
    __half l = __float2half_rn(x - __half2float(h));
    size_t base = (size_t)m * KCAT + c;
    g_Bcat[base]             = h;
    g_Bcat[base + D_EMB]     = h;
    g_Bcat[base + 2 * D_EMB] = l;
}

__global__ void k_cvt_T(const float* __restrict__ T) {
    int i = blockIdx.x * blockDim.x + threadIdx.x;
    if (i >= D_EMB * D_EMB) return;
    int k = i / D_EMB, j = i % D_EMB;
    float x = T[i];
    __half h = __float2half_rn(x);
    __half l = __float2half_rn(x - __half2float(h));
    g_B2[(size_t)k * D_EMB + j]               = h;
    g_B2[(size_t)(k + D_EMB) * D_EMB + j]     = l;
    g_B2[(size_t)(k + 2 * D_EMB) * D_EMB + j] = h;
}

// ---------------- wmma GEMM: CTA 128x128 (4 warps), warp tile 64x64, k-chunk 32 --
// Double-buffered smem + register prefetch (R5-proven schedule), 2 CTAs/SM,
// ~237 regs/thread (no launch_bounds cap -> no spills).
//   iter it: STS(it,buf) -> sync -> LDG(it+1 into regs) -> compute(it,buf)
// MODE 0: P   = Bcat @ B2        (M=8192, N=256,  K=768)   B row-major [K,N]
// MODE 1: S   = Acat @ Bcat^T    (M=8192, N=8192, K=768)   B col-major [N,K]
// MODE 2: M1  = gated @ Xh       (M=8192, N=1024, K=8192)  B row-major [K,N]
// MODE 3: out = M1h @ Gh         (M=8192, N=1024, K=1024)  B row-major [K,N]
template <int MODE>
__global__ void gemm_wmma6(const float* __restrict__ aux, float* __restrict__ outf) {
    constexpr bool B_COL = (MODE == 1);
    constexpr int K    = (MODE <= 1) ? KCAT : (MODE == 2 ? N_CELLS : D_GENE);
    constexpr int NK   = K / 32;
    constexpr int Ndim = (MODE == 0) ? D_EMB : (MODE == 1 ? N_CELLS : D_GENE);
    constexpr int LDA  = 40;                  // A pitch (halves): 32 data + 8 pad

    const __half* __restrict__ A =
        (MODE == 0) ? g_Bcat : (MODE == 1) ? g_Acat : (MODE == 2) ? g_gated : g_M1h;
    const __half* __restrict__ B =
        (MODE == 0) ? g_B2 : (MODE == 1) ? g_Bcat : (MODE == 2) ? g_Xh : g_Gh;

    __shared__ __align__(16) __half As[2][128 * 40];  // 2 x 10240 B
    __shared__ __align__(16) __half Bs[2][5120];      // 2 x 10240 B (col 128x40; row 32x136)
    __shared__ __align__(16) float  epbuf[4][320];    // 5120 B  => 46080 B/CTA

    const int tid  = threadIdx.x;    // 0..127
    const int lane = tid & 31;
    const int w    = tid >> 5;       // 0..3
    const int wm   = w >> 1;         // 0..1 -> m offset wm*64
    const int wn   = w & 1;          // 0..1 -> n offset wn*64
    const size_t gm0 = (size_t)blockIdx.y * 128;
    const size_t gn0 = (size_t)blockIdx.x * 128;

    wmma::fragment<wmma::accumulator, 16, 16, 16, float> acc[4][4];
#pragma unroll
    for (int i = 0; i < 4; i++)
#pragma unroll
        for (int j = 0; j < 4; j++) wmma::fill_fragment(acc[i][j], 0.0f);

    // ---- register staging: 4 float4 for A, 4 for B (32 regs) ----
    float4 rA[4], rB[4];

    auto fetch = [&](int k0) {
#pragma unroll
        for (int j = 0; j < 4; j++) {
            int idx = tid + j * 128;
            int row = idx >> 2, ch = idx & 3;    // A: 128 rows x 4 chunks(16B)
            rA[j] = *(const float4*)(A + (gm0 + row) * (size_t)K + k0 + ch * 8);
        }
        if (B_COL) {
#pragma unroll
            for (int j = 0; j < 4; j++) {
                int idx = tid + j * 128;
                int row = idx >> 2, ch = idx & 3;
                rB[j] = *(const float4*)(B + (gn0 + row) * (size_t)K + k0 + ch * 8);
            }
        } else {
#pragma unroll
            for (int j = 0; j < 4; j++) {
                int idx = tid + j * 128;
                int row = idx >> 4, ch = idx & 15;   // 32 rows x 16 chunks
                rB[j] = *(const float4*)(B + (size_t)(k0 + row) * Ndim + gn0 + ch * 8);
            }
        }
    };
    auto store = [&](int buf) {
#pragma unroll
        for (int j = 0; j < 4; j++) {
            int idx = tid + j * 128;
            int row = idx >> 2, ch = idx & 3;
            *(float4*)(&As[buf][row * LDA + ch * 8]) = rA[j];
        }
        if (B_COL) {
#pragma unroll
            for (int j = 0; j < 4; j++) {
                int idx = tid + j * 128;
                int row = idx >> 2, ch = idx & 3;
                *(float4*)(&Bs[buf][row * 40 + ch * 8]) = rB[j];
            }
        } else {
#pragma unroll
            for (int j = 0; j < 4; j++) {
                int idx = tid + j * 128;
                int row = idx >> 4, ch = idx & 15;
                *(float4*)(&Bs[buf][row * 136 + ch * 8]) = rB[j];
            }
        }
    };

    fetch(0);

#pragma unroll 1
    for (int it = 0; it < NK; ++it) {
        const int buf = it & 1;
        store(buf);
        __syncthreads();   // tiles visible; compute(it-2) on this buf done before sync(it-1)
        if (it + 1 < NK) fetch((it + 1) * 32);   // lands under compute(it)

#pragma unroll
        for (int kk = 0; kk < 32; kk += 16) {
            if constexpr (B_COL) {
                wmma::fragment<wmma::matrix_b, 16, 16, 16, __half, wmma::col_major> b[4];
#pragma unroll
                for (int nt = 0; nt < 4; nt++)
                    wmma::load_matrix_sync(b[nt], &Bs[buf][(wn * 64 + nt * 16) * 40 + kk], 40);
#pragma unroll
                for (int mt = 0; mt < 4; mt++) {
                    wmma::fragment<wmma::matrix_a, 16, 16, 16, __half, wmma::row_major> a;
                    wmma::load_matrix_sync(a, &As[buf][(wm * 64 + mt * 16) * LDA + kk], LDA);
#pragma unroll
                    for (int nt = 0; nt < 4; nt++)
                        wmma::mma_sync(acc[mt][nt], a, b[nt], acc[mt][nt]);
                }
            } else {
                wmma::fragment<wmma::matrix_b, 16, 16, 16, __half, wmma::row_major> b[4];
#pragma unroll
                for (int nt = 0; nt < 4; nt++)
                    wmma::load_matrix_sync(b[nt], &Bs[buf][kk * 136 + wn * 64 + nt * 16], 136);
#pragma unroll
                for (int mt = 0; mt < 4; mt++) {
                    wmma::fragment<wmma::matrix_a, 16, 16, 16, __half, wmma::row_major> a;
                    wmma::load_matrix_sync(a, &As[buf][(wm * 64 + mt * 16) * LDA + kk], LDA);
#pragma unroll
                    for (int nt = 0; nt < 4; nt++)
                        wmma::mma_sync(acc[mt][nt], a, b[nt], acc[mt][nt]);
                }
            }
        }
    }

    // ---------------- epilogue (per-warp staging, proven pattern) ----------------
    const int r  = lane >> 1;
    const int cb = (lane & 1) * 8;
#pragma unroll
    for (int mt = 0; mt < 4; mt++) {
        const size_t gr = gm0 + wm * 64 + mt * 16 + r;
#pragma unroll
        for (int nt = 0; nt < 4; nt++) {
            wmma::store_matrix_sync(&epbuf[w][0], acc[mt][nt], 20, wmma::mem_row_major);
            __syncwarp();
            const size_t gc = gn0 + wn * 64 + nt * 16 + cb;
            float v[8];
#pragma unroll
            for (int e = 0; e < 8; e++) v[e] = epbuf[w][r * 20 + cb + e];

            if constexpr (MODE == 0) {
                __half2 hh[4], ll[4];
#pragma unroll
                for (int e = 0; e < 4; e++) {
                    __half h0 = __float2half_rn(v[e * 2]);
                    __half h1 = __float2half_rn(v[e * 2 + 1]);
                    hh[e] = __halves2half2(h0, h1);
                    ll[e] = __halves2half2(
                        __float2half_rn(v[e * 2]     - __half2float(h0)),
                        __float2half_rn(v[e * 2 + 1] - __half2float(h1)));
                }
                size_t base = gr * KCAT + gc;
                *(uint4*)(g_Acat + base)             = *(uint4*)hh;
                *(uint4*)(g_Acat + base + D_EMB)     = *(uint4*)ll;
                *(uint4*)(g_Acat + base + 2 * D_EMB) = *(uint4*)hh;
            } else if constexpr (MODE == 1) {
                const float* prow = aux + gr * (size_t)N_CELLS + gc;
                float4 p0 = __ldcs((const float4*)prow);
                float4 p1 = __ldcs((const float4*)(prow + 4));
                float pv[8] = {p0.x, p0.y, p0.z, p0.w, p1.x, p1.y, p1.z, p1.w};
                __half2 o[4];
#pragma unroll
                for (int e = 0; e < 4; e++) {
                    float s0 = __expf(pv[e * 2]     * -1e-4f) / (1.0f + __expf(-v[e * 2]));
                    float s1 = __expf(pv[e * 2 + 1] * -1e-4f) / (1.0f + __expf(-v[e * 2 + 1]));
                    o[e] = __floats2half2_rn(s0, s1);
                }
                *(uint4*)(g_gated + gr * (size_t)N_CELLS + gc) = *(uint4*)o;
            } else if constexpr (MODE == 2) {
                __half2 o[4];
#pragma unroll
                for (int e = 0; e < 4; e++)
                    o[e] = __floats2half2_rn(v[e * 2], v[e * 2 + 1]);
                *(uint4*)(g_M1h + gr * D_GENE + gc) = *(uint4*)o;
            } else {
                float4 o0 = make_float4(v[0] * (1.0f / 1024.0f), v[1] * (1.0f / 1024.0f),
                                        v[2] * (1.0f / 1024.0f), v[3] * (1.0f / 1024.0f));
                float4 o1 = make_float4(v[4] * (1.0f / 1024.0f), v[5] * (1.0f / 1024.0f),
                                        v[6] * (1.0f / 1024.0f), v[7] * (1.0f / 1024.0f));
                *(float4*)(outf + gr * D_GENE + gc)     = o0;
                *(float4*)(outf + gr * D_GENE + gc + 4) = o1;
            }
            __syncwarp();
        }
    }
}

// ---------------- launch ----------------
extern "C" void kernel_launch(void* const* d_in, const int* in_sizes, int n_in,
                              void* d_out, int out_size) {
    const float* expr = (const float*)d_in[0];
    const float* enc  = (const float*)d_in[1];
    const float* pd   = (const float*)d_in[2];
    const float* T    = (const float*)d_in[3];
    const float* gr   = (const float*)d_in[4];
    float* out = (float*)d_out;

    // Order chosen so the 4th launch (ncu capture slot) is the dominant GEMM1.
    k_cvt_enc<<<(N_CELLS * D_EMB) / 256, 256>>>(enc);
    k_cvt_T<<<(D_EMB * D_EMB) / 256, 256>>>(T);
    gemm_wmma6<0><<<dim3(D_EMB / 128,  N_CELLS / 128), 128>>>(nullptr, nullptr);
    gemm_wmma6<1><<<dim3(N_CELLS / 128, N_CELLS / 128), 128>>>(pd, nullptr);
    k_cvt_expr<<<(N_CELLS * D_GENE) / 256, 256>>>(expr);
    k_cvt_gr<<<(D_GENE * D_GENE) / 256, 256>>>(gr);
    gemm_wmma6<2><<<dim3(D_GENE / 128, N_CELLS / 128), 128>>>(nullptr, nullptr);
    gemm_wmma6<3><<<dim3(D_GENE / 128, N_CELLS / 128), 128>>>(nullptr, out);
}

// round 11
// speedup vs baseline: 2.0583x; 1.3210x over previous
#include <cuda_runtime.h>
#include <cuda_fp16.h>
#include <mma.h>
#include <cstdint>

using namespace nvcuda;

#define N_CELLS 8192
#define D_GENE  1024
#define D_EMB   256
#define KCAT    768   // [hi | lo | hi] split concat along K

// ---------------- scratch (device globals; no allocation allowed) ----------------
__device__ __half g_Bcat[(size_t)N_CELLS * KCAT];   // [Eh | Eh | El]   [N,K]
__device__ __half g_Acat[(size_t)N_CELLS * KCAT];   // [Ph | Pl | Ph]   [M,K]
__device__ __half g_B2[(size_t)KCAT * D_EMB];       // [Th ; Tl ; Th]   [K,N]
__device__ __half g_Xh[(size_t)N_CELLS * D_GENE];   // expression fp16  [K,N]
__device__ __half g_Gh[(size_t)D_GENE * D_GENE];    // gene_response    [K,N]
__device__ __half g_gated[(size_t)N_CELLS * N_CELLS]; // gated matrix   128 MB
__device__ __half g_M1h[(size_t)N_CELLS * D_GENE];  // (gated@expr)

// ---------------- conversion kernels (R1 originals, proven) ----------------
__global__ void k_cvt_expr(const float* __restrict__ in) {
    int i = blockIdx.x * blockDim.x + threadIdx.x;
    if (i < N_CELLS * D_GENE) g_Xh[i] = __float2half_rn(in[i]);
}

__global__ void k_cvt_gr(const float* __restrict__ in) {
    int i = blockIdx.x * blockDim.x + threadIdx.x;
    if (i < D_GENE * D_GENE) g_Gh[i] = __float2half_rn(in[i]);
}

__global__ void k_cvt_enc(const float* __restrict__ enc) {
    int i = blockIdx.x * blockDim.x + threadIdx.x;
    if (i >= N_CELLS * D_EMB) return;
    int m = i / D_EMB, c = i % D_EMB;
    float x = enc[i];
    __half h = __float2half_rn(x);
    __half l = __float2half_rn(x - __half2float(h));
    size_t base = (size_t)m * KCAT + c;
    g_Bcat[base]             = h;
    g_Bcat[base + D_EMB]     = h;
    g_Bcat[base + 2 * D_EMB] = l;
}

__global__ void k_cvt_T(const float* __restrict__ T) {
    int i = blockIdx.x * blockDim.x + threadIdx.x;
    if (i >= D_EMB * D_EMB) return;
    int k = i / D_EMB, j = i % D_EMB;
    float x = T[i];
    __half h = __float2half_rn(x);
    __half l = __float2half_rn(x - __half2float(h));
    g_B2[(size_t)k * D_EMB + j]               = h;
    g_B2[(size_t)(k + D_EMB) * D_EMB + j]     = l;
    g_B2[(size_t)(k + 2 * D_EMB) * D_EMB + j] = h;
}

// gate math: spatial = exp(-pd/1e4) = 1 - pd*1e-4 (Taylor, err<5e-9 for pd in [0,1]);
// sigmoid saturates for |v|>10 (err<4.5e-5 < fp16 ulp of gated) -> MUFU on ~3% only.
__device__ __forceinline__ float gate_fn(float pd, float v) {
    float sp = fmaf(pd, -1e-4f, 1.0f);
    float sig;
    if (fabsf(v) < 10.0f)
        sig = __fdividef(1.0f, 1.0f + __expf(-v));
    else
        sig = (v > 0.0f) ? 1.0f : 0.0f;
    return sp * sig;
}

// ---------------- wmma GEMM: CTA 128x128 (4 warps), warp tile 64x64, k-chunk 32 --
// Double-buffered smem + register prefetch, 2 CTAs/SM (proven R10 structure).
//   iter it: STS(it,buf) -> sync -> LDG(it+1 into regs) -> compute(it,buf)
// MODE 0: P   = Bcat @ B2        (M=8192, N=256,  K=768)   B row-major [K,N]
// MODE 1: S   = Acat @ Bcat^T    (M=8192, N=8192, K=768)   B col-major [N,K]
// MODE 2: M1  = gated @ Xh       (M=8192, N=1024, K=8192)  B row-major [K,N]
// MODE 3: out = M1h @ Gh         (M=8192, N=1024, K=1024)  B row-major [K,N]
template <int MODE>
__global__ void gemm_wmma6(const float* __restrict__ aux, float* __restrict__ outf) {
    constexpr bool B_COL = (MODE == 1);
    constexpr int K    = (MODE <= 1) ? KCAT : (MODE == 2 ? N_CELLS : D_GENE);
    constexpr int NK   = K / 32;
    constexpr int Ndim = (MODE == 0) ? D_EMB : (MODE == 1 ? N_CELLS : D_GENE);
    constexpr int LDA  = 40;                  // A pitch (halves): 32 data + 8 pad

    const __half* __restrict__ A =
        (MODE == 0) ? g_Bcat : (MODE == 1) ? g_Acat : (MODE == 2) ? g_gated : g_M1h;
    const __half* __restrict__ B =
        (MODE == 0) ? g_B2 : (MODE == 1) ? g_Bcat : (MODE == 2) ? g_Xh : g_Gh;

    __shared__ __align__(16) __half As[2][128 * 40];  // 2 x 10240 B
    __shared__ __align__(16) __half Bs[2][5120];      // 2 x 10240 B (col 128x40; row 32x136)
    __shared__ __align__(16) float  epbuf[4][320];    // 5120 B  => 46080 B/CTA

    const int tid  = threadIdx.x;    // 0..127
    const int lane = tid & 31;
    const int w    = tid >> 5;       // 0..3
    const int wm   = w >> 1;         // 0..1 -> m offset wm*64
    const int wn   = w & 1;          // 0..1 -> n offset wn*64
    const size_t gm0 = (size_t)blockIdx.y * 128;
    const size_t gn0 = (size_t)blockIdx.x * 128;

    wmma::fragment<wmma::accumulator, 16, 16, 16, float> acc[4][4];
#pragma unroll
    for (int i = 0; i < 4; i++)
#pragma unroll
        for (int j = 0; j < 4; j++) wmma::fill_fragment(acc[i][j], 0.0f);

    // ---- register staging: 4 float4 for A, 4 for B (32 regs) ----
    float4 rA[4], rB[4];

    auto fetch = [&](int k0) {
#pragma unroll
        for (int j = 0; j < 4; j++) {
            int idx = tid + j * 128;
            int row = idx >> 2, ch = idx & 3;    // A: 128 rows x 4 chunks(16B)
            rA[j] = *(const float4*)(A + (gm0 + row) * (size_t)K + k0 + ch * 8);
        }
        if (B_COL) {
#pragma unroll
            for (int j = 0; j < 4; j++) {
                int idx = tid + j * 128;
                int row = idx >> 2, ch = idx & 3;
                rB[j] = *(const float4*)(B + (gn0 + row) * (size_t)K + k0 + ch * 8);
            }
        } else {
#pragma unroll
            for (int j = 0; j < 4; j++) {
                int idx = tid + j * 128;
                int row = idx >> 4, ch = idx & 15;   // 32 rows x 16 chunks
                rB[j] = *(const float4*)(B + (size_t)(k0 + row) * Ndim + gn0 + ch * 8);
            }
        }
    };
    auto store = [&](int buf) {
#pragma unroll
        for (int j = 0; j < 4; j++) {
            int idx = tid + j * 128;
            int row = idx >> 2, ch = idx & 3;
            *(float4*)(&As[buf][row * LDA + ch * 8]) = rA[j];
        }
        if (B_COL) {
#pragma unroll
            for (int j = 0; j < 4; j++) {
                int idx = tid + j * 128;
                int row = idx >> 2, ch = idx & 3;
                *(float4*)(&Bs[buf][row * 40 + ch * 8]) = rB[j];
            }
        } else {
#pragma unroll
            for (int j = 0; j < 4; j++) {
                int idx = tid + j * 128;
                int row = idx >> 4, ch = idx & 15;
                *(float4*)(&Bs[buf][row * 136 + ch * 8]) = rB[j];
            }
        }
    };

    fetch(0);

#pragma unroll 1
    for (int it = 0; it < NK; ++it) {
        const int buf = it & 1;
        store(buf);
        __syncthreads();   // tiles visible; compute(it-2) on this buf done before sync(it-1)
        if (it + 1 < NK) fetch((it + 1) * 32);   // lands under compute(it)

#pragma unroll
        for (int kk = 0; kk < 32; kk += 16) {
            if constexpr (B_COL) {
                wmma::fragment<wmma::matrix_b, 16, 16, 16, __half, wmma::col_major> b[4];
#pragma unroll
                for (int nt = 0; nt < 4; nt++)
                    wmma::load_matrix_sync(b[nt], &Bs[buf][(wn * 64 + nt * 16) * 40 + kk], 40);
#pragma unroll
                for (int mt = 0; mt < 4; mt++) {
                    wmma::fragment<wmma::matrix_a, 16, 16, 16, __half, wmma::row_major> a;
                    wmma::load_matrix_sync(a, &As[buf][(wm * 64 + mt * 16) * LDA + kk], LDA);
#pragma unroll
                    for (int nt = 0; nt < 4; nt++)
                        wmma::mma_sync(acc[mt][nt], a, b[nt], acc[mt][nt]);
                }
            } else {
                wmma::fragment<wmma::matrix_b, 16, 16, 16, __half, wmma::row_major> b[4];
#pragma unroll
                for (int nt = 0; nt < 4; nt++)
                    wmma::load_matrix_sync(b[nt], &Bs[buf][kk * 136 + wn * 64 + nt * 16], 136);
#pragma unroll
                for (int mt = 0; mt < 4; mt++) {
                    wmma::fragment<wmma::matrix_a, 16, 16, 16, __half, wmma::row_major> a;
                    wmma::load_matrix_sync(a, &As[buf][(wm * 64 + mt * 16) * LDA + kk], LDA);
#pragma unroll
                    for (int nt = 0; nt < 4; nt++)
                        wmma::mma_sync(acc[mt][nt], a, b[nt], acc[mt][nt]);
                }
            }
        }
    }

    // ---------------- epilogue (per-warp staging, proven pattern) ----------------
    const int r  = lane >> 1;
    const int cb = (lane & 1) * 8;
#pragma unroll
    for (int mt = 0; mt < 4; mt++) {
        const size_t gr = gm0 + wm * 64 + mt * 16 + r;
#pragma unroll
        for (int nt = 0; nt < 4; nt++) {
            wmma::store_matrix_sync(&epbuf[w][0], acc[mt][nt], 20, wmma::mem_row_major);
            __syncwarp();
            const size_t gc = gn0 + wn * 64 + nt * 16 + cb;
            float v[8];
#pragma unroll
            for (int e = 0; e < 8; e++) v[e] = epbuf[w][r * 20 + cb + e];

            if constexpr (MODE == 0) {
                __half2 hh[4], ll[4];
#pragma unroll
                for (int e = 0; e < 4; e++) {
                    __half h0 = __float2half_rn(v[e * 2]);
                    __half h1 = __float2half_rn(v[e * 2 + 1]);
                    hh[e] = __halves2half2(h0, h1);
                    ll[e] = __halves2half2(
                        __float2half_rn(v[e * 2]     - __half2float(h0)),
                        __float2half_rn(v[e * 2 + 1] - __half2float(h1)));
                }
                size_t base = gr * KCAT + gc;
                *(uint4*)(g_Acat + base)             = *(uint4*)hh;
                *(uint4*)(g_Acat + base + D_EMB)     = *(uint4*)ll;
                *(uint4*)(g_Acat + base + 2 * D_EMB) = *(uint4*)hh;
            } else if constexpr (MODE == 1) {
                const float* prow = aux + gr * (size_t)N_CELLS + gc;
                float4 p0 = __ldcs((const float4*)prow);
                float4 p1 = __ldcs((const float4*)(prow + 4));
                float pv[8] = {p0.x, p0.y, p0.z, p0.w, p1.x, p1.y, p1.z, p1.w};
                __half2 o[4];
#pragma unroll
                for (int e = 0; e < 4; e++) {
                    float s0 = gate_fn(pv[e * 2],     v[e * 2]);
                    float s1 = gate_fn(pv[e * 2 + 1], v[e * 2 + 1]);
                    o[e] = __floats2half2_rn(s0, s1);
                }
                *(uint4*)(g_gated + gr * (size_t)N_CELLS + gc) = *(uint4*)o;
            } else if constexpr (MODE == 2) {
                __half2 o[4];
#pragma unroll
                for (int e = 0; e < 4; e++)
                    o[e] = __floats2half2_rn(v[e * 2], v[e * 2 + 1]);
                *(uint4*)(g_M1h + gr * D_GENE + gc) = *(uint4*)o;
            } else {
                float4 o0 = make_float4(v[0] * (1.0f / 1024.0f), v[1] * (1.0f / 1024.0f),
                                        v[2] * (1.0f / 1024.0f), v[3] * (1.0f / 1024.0f));
                float4 o1 = make_float4(v[4] * (1.0f / 1024.0f), v[5] * (1.0f / 1024.0f),
                                        v[6] * (1.0f / 1024.0f), v[7] * (1.0f / 1024.0f));
                *(float4*)(outf + gr * D_GENE + gc)     = o0;
                *(float4*)(outf + gr * D_GENE + gc + 4) = o1;
            }
            __syncwarp();
        }
    }
}

// ---------------- launch ----------------
extern "C" void kernel_launch(void* const* d_in, const int* in_sizes, int n_in,
                              void* d_out, int out_size) {
    const float* expr = (const float*)d_in[0];
    const float* enc  = (const float*)d_in[1];
    const float* pd   = (const float*)d_in[2];
    const float* T    = (const float*)d_in[3];
    const float* gr   = (const float*)d_in[4];
    float* out = (float*)d_out;

    // Order chosen so the 4th launch (ncu capture slot) is the dominant GEMM1.
    k_cvt_enc<<<(N_CELLS * D_EMB) / 256, 256>>>(enc);
    k_cvt_T<<<(D_EMB * D_EMB) / 256, 256>>>(T);
    gemm_wmma6<0><<<dim3(D_EMB / 128,  N_CELLS / 128), 128>>>(nullptr, nullptr);
    gemm_wmma6<1><<<dim3(N_CELLS / 128, N_CELLS / 128), 128>>>(pd, nullptr);
    k_cvt_expr<<<(N_CELLS * D_GENE) / 256, 256>>>(expr);
    k_cvt_gr<<<(D_GENE * D_GENE) / 256, 256>>>(gr);
    gemm_wmma6<2><<<dim3(D_GENE / 128, N_CELLS / 128), 128>>>(nullptr, nullptr);
    gemm_wmma6<3><<<dim3(D_GENE / 128, N_CELLS / 128), 128>>>(nullptr, out);
}

// round 12
// speedup vs baseline: 2.2231x; 1.0801x over previous
#include <cuda_runtime.h>
#include <cuda_fp16.h>
#include <cuda_pipeline.h>
#include <mma.h>
#include <cstdint>

using namespace nvcuda;

#define N_CELLS 8192
#define D_GENE  1024
#define D_EMB   256
#define KCAT    768   // [hi | lo | hi] split concat along K

// ---------------- scratch (device globals; no allocation allowed) ----------------
__device__ __half g_Bcat[(size_t)N_CELLS * KCAT];   // [Eh | Eh | El]   [N,K]
__device__ __half g_Acat[(size_t)N_CELLS * KCAT];   // [Ph | Pl | Ph]   [M,K]
__device__ __half g_B2[(size_t)KCAT * D_EMB];       // [Th ; Tl ; Th]   [K,N]
__device__ __half g_Xh[(size_t)N_CELLS * D_GENE];   // expression fp16  [K,N]
__device__ __half g_Gh[(size_t)D_GENE * D_GENE];    // gene_response    [K,N]
__device__ __half g_gated[(size_t)N_CELLS * N_CELLS]; // gated matrix   128 MB
__device__ __half g_M1h[(size_t)N_CELLS * D_GENE];  // (gated@expr)

// ---------------- conversion kernels (R1 originals, proven) ----------------
__global__ void k_cvt_expr(const float* __restrict__ in) {
    int i = blockIdx.x * blockDim.x + threadIdx.x;
    if (i < N_CELLS * D_GENE) g_Xh[i] = __float2half_rn(in[i]);
}

__global__ void k_cvt_gr(const float* __restrict__ in) {
    int i = blockIdx.x * blockDim.x + threadIdx.x;
    if (i < D_GENE * D_GENE) g_Gh[i] = __float2half_rn(in[i]);
}

__global__ void k_cvt_enc(const float* __restrict__ enc) {
    int i = blockIdx.x * blockDim.x + threadIdx.x;
    if (i >= N_CELLS * D_EMB) return;
    int m = i / D_EMB, c = i % D_EMB;
    float x = enc[i];
    __half h = __float2half_rn(x);
    __half l = __float2half_rn(x - __half2float(h));
    size_t base = (size_t)m * KCAT + c;
    g_Bcat[base]             = h;
    g_Bcat[base + D_EMB]     = h;
    g_Bcat[base + 2 * D_EMB] = l;
}

__global__ void k_cvt_T(const float* __restrict__ T) {
    int i = blockIdx.x * blockDim.x + threadIdx.x;
    if (i >= D_EMB * D_EMB) return;
    int k = i / D_EMB, j = i % D_EMB;
    float x = T[i];
    __half h = __float2half_rn(x);
    __half l = __float2half_rn(x - __half2float(h));
    g_B2[(size_t)k * D_EMB + j]               = h;
    g_B2[(size_t)(k + D_EMB) * D_EMB + j]     = l;
    g_B2[(size_t)(k + 2 * D_EMB) * D_EMB + j] = h;
}

// gate math: spatial = exp(-pd/1e4) = 1 - pd*1e-4 (Taylor, err<5e-9 for pd in [0,1]);
// sigmoid saturates for |v|>10 (err<4.5e-5 < fp16 ulp of gated) -> MUFU on ~3% only.
__device__ __forceinline__ float gate_fn(float pd, float v) {
    float sp = fmaf(pd, -1e-4f, 1.0f);
    float sig;
    if (fabsf(v) < 10.0f)
        sig = __fdividef(1.0f, 1.0f + __expf(-v));
    else
        sig = (v > 0.0f) ? 1.0f : 0.0f;
    return sp * sig;
}

// ---------------- wmma GEMM: CTA 128x128 (4 warps), warp tile 64x64, k-chunk 32 --
// SINGLE DELTA vs R11: loads via __pipeline_memcpy_async (global -> smem direct),
// removing the LDG->RF->STS double pass through L1. Everything else identical.
//   iter it: wait_prior(0) -> sync -> issue copy(it+1 -> buf^1) -> compute(it, buf)
// MODE 0: P   = Bcat @ B2        (M=8192, N=256,  K=768)   B row-major [K,N]
// MODE 1: S   = Acat @ Bcat^T    (M=8192, N=8192, K=768)   B col-major [N,K]
// MODE 2: M1  = gated @ Xh       (M=8192, N=1024, K=8192)  B row-major [K,N]
// MODE 3: out = M1h @ Gh         (M=8192, N=1024, K=1024)  B row-major [K,N]
template <int MODE>
__global__ void gemm_wmma7(const float* __restrict__ aux, float* __restrict__ outf) {
    constexpr bool B_COL = (MODE == 1);
    constexpr int K    = (MODE <= 1) ? KCAT : (MODE == 2 ? N_CELLS : D_GENE);
    constexpr int NK   = K / 32;
    constexpr int Ndim = (MODE == 0) ? D_EMB : (MODE == 1 ? N_CELLS : D_GENE);
    constexpr int LDA  = 40;                  // A pitch (halves): 32 data + 8 pad

    const __half* __restrict__ A =
        (MODE == 0) ? g_Bcat : (MODE == 1) ? g_Acat : (MODE == 2) ? g_gated : g_M1h;
    const __half* __restrict__ B =
        (MODE == 0) ? g_B2 : (MODE == 1) ? g_Bcat : (MODE == 2) ? g_Xh : g_Gh;

    __shared__ __align__(16) __half As[2][128 * 40];  // 2 x 10240 B
    __shared__ __align__(16) __half Bs[2][5120];      // 2 x 10240 B (col 128x40; row 32x136)
    __shared__ __align__(16) float  epbuf[4][320];    // 5120 B  => 46080 B/CTA

    const int tid  = threadIdx.x;    // 0..127
    const int lane = tid & 31;
    const int w    = tid >> 5;       // 0..3
    const int wm   = w >> 1;         // 0..1 -> m offset wm*64
    const int wn   = w & 1;          // 0..1 -> n offset wn*64
    const size_t gm0 = (size_t)blockIdx.y * 128;
    const size_t gn0 = (size_t)blockIdx.x * 128;

    wmma::fragment<wmma::accumulator, 16, 16, 16, float> acc[4][4];
#pragma unroll
    for (int i = 0; i < 4; i++)
#pragma unroll
        for (int j = 0; j < 4; j++) wmma::fill_fragment(acc[i][j], 0.0f);

    // ---- async stage copy: global -> smem, 16B granules ----
    auto load_stage = [&](int it, int buf) {
        const int k0 = it * 32;
#pragma unroll
        for (int j = 0; j < 4; j++) {
            int idx = tid + j * 128;
            int row = idx >> 2, ch = idx & 3;    // A: 128 rows x 4 chunks(16B)
            __pipeline_memcpy_async(&As[buf][row * LDA + ch * 8],
                                    A + (gm0 + row) * (size_t)K + k0 + ch * 8, 16);
        }
        if (B_COL) {
#pragma unroll
            for (int j = 0; j < 4; j++) {
                int idx = tid + j * 128;
                int row = idx >> 2, ch = idx & 3;
                __pipeline_memcpy_async(&Bs[buf][row * 40 + ch * 8],
                                        B + (gn0 + row) * (size_t)K + k0 + ch * 8, 16);
            }
        } else {
#pragma unroll
            for (int j = 0; j < 4; j++) {
                int idx = tid + j * 128;
                int row = idx >> 4, ch = idx & 15;   // 32 rows x 16 chunks
                __pipeline_memcpy_async(&Bs[buf][row * 136 + ch * 8],
                                        B + (size_t)(k0 + row) * Ndim + gn0 + ch * 8, 16);
            }
        }
        __pipeline_commit();
    };

    load_stage(0, 0);

#pragma unroll 1
    for (int it = 0; it < NK; ++it) {
        const int buf = it & 1;
        __pipeline_wait_prior(0);   // copy into `buf` (issued at it-1) complete
        __syncthreads();            // visible to all warps; reads of buf^1 (it-1) done
        if (it + 1 < NK) load_stage(it + 1, buf ^ 1);   // lands under compute(it)

#pragma unroll
        for (int kk = 0; kk < 32; kk += 16) {
            if constexpr (B_COL) {
                wmma::fragment<wmma::matrix_b, 16, 16, 16, __half, wmma::col_major> b[4];
#pragma unroll
                for (int nt = 0; nt < 4; nt++)
                    wmma::load_matrix_sync(b[nt], &Bs[buf][(wn * 64 + nt * 16) * 40 + kk], 40);
#pragma unroll
                for (int mt = 0; mt < 4; mt++) {
                    wmma::fragment<wmma::matrix_a, 16, 16, 16, __half, wmma::row_major> a;
                    wmma::load_matrix_sync(a, &As[buf][(wm * 64 + mt * 16) * LDA + kk], LDA);
#pragma unroll
                    for (int nt = 0; nt < 4; nt++)
                        wmma::mma_sync(acc[mt][nt], a, b[nt], acc[mt][nt]);
                }
            } else {
                wmma::fragment<wmma::matrix_b, 16, 16, 16, __half, wmma::row_major> b[4];
#pragma unroll
                for (int nt = 0; nt < 4; nt++)
                    wmma::load_matrix_sync(b[nt], &Bs[buf][kk * 136 + wn * 64 + nt * 16], 136);
#pragma unroll
                for (int mt = 0; mt < 4; mt++) {
                    wmma::fragment<wmma::matrix_a, 16, 16, 16, __half, wmma::row_major> a;
                    wmma::load_matrix_sync(a, &As[buf][(wm * 64 + mt * 16) * LDA + kk], LDA);
#pragma unroll
                    for (int nt = 0; nt < 4; nt++)
                        wmma::mma_sync(acc[mt][nt], a, b[nt], acc[mt][nt]);
                }
            }
        }
    }

    // ---------------- epilogue (per-warp staging, proven pattern) ----------------
    const int r  = lane >> 1;
    const int cb = (lane & 1) * 8;
#pragma unroll
    for (int mt = 0; mt < 4; mt++) {
        const size_t gr = gm0 + wm * 64 + mt * 16 + r;
#pragma unroll
        for (int nt = 0; nt < 4; nt++) {
            wmma::store_matrix_sync(&epbuf[w][0], acc[mt][nt], 20, wmma::mem_row_major);
            __syncwarp();
            const size_t gc = gn0 + wn * 64 + nt * 16 + cb;
            float v[8];
#pragma unroll
            for (int e = 0; e < 8; e++) v[e] = epbuf[w][r * 20 + cb + e];

            if constexpr (MODE == 0) {
                __half2 hh[4], ll[4];
#pragma unroll
                for (int e = 0; e < 4; e++) {
                    __half h0 = __float2half_rn(v[e * 2]);
                    __half h1 = __float2half_rn(v[e * 2 + 1]);
                    hh[e] = __halves2half2(h0, h1);
                    ll[e] = __halves2half2(
                        __float2half_rn(v[e * 2]     - __half2float(h0)),
                        __float2half_rn(v[e * 2 + 1] - __half2float(h1)));
                }
                size_t base = gr * KCAT + gc;
                *(uint4*)(g_Acat + base)             = *(uint4*)hh;
                *(uint4*)(g_Acat + base + D_EMB)     = *(uint4*)ll;
                *(uint4*)(g_Acat + base + 2 * D_EMB) = *(uint4*)hh;
            } else if constexpr (MODE == 1) {
                const float* prow = aux + gr * (size_t)N_CELLS + gc;
                float4 p0 = __ldcs((const float4*)prow);
                float4 p1 = __ldcs((const float4*)(prow + 4));
                float pv[8] = {p0.x, p0.y, p0.z, p0.w, p1.x, p1.y, p1.z, p1.w};
                __half2 o[4];
#pragma unroll
                for (int e = 0; e < 4; e++) {
                    float s0 = gate_fn(pv[e * 2],     v[e * 2]);
                    float s1 = gate_fn(pv[e * 2 + 1], v[e * 2 + 1]);
                    o[e] = __floats2half2_rn(s0, s1);
                }
                *(uint4*)(g_gated + gr * (size_t)N_CELLS + gc) = *(uint4*)o;
            } else if constexpr (MODE == 2) {
                __half2 o[4];
#pragma unroll
                for (int e = 0; e < 4; e++)
                    o[e] = __floats2half2_rn(v[e * 2], v[e * 2 + 1]);
                *(uint4*)(g_M1h + gr * D_GENE + gc) = *(uint4*)o;
            } else {
                float4 o0 = make_float4(v[0] * (1.0f / 1024.0f), v[1] * (1.0f / 1024.0f),
                                        v[2] * (1.0f / 1024.0f), v[3] * (1.0f / 1024.0f));
                float4 o1 = make_float4(v[4] * (1.0f / 1024.0f), v[5] * (1.0f / 1024.0f),
                                        v[6] * (1.0f / 1024.0f), v[7] * (1.0f / 1024.0f));
                *(float4*)(outf + gr * D_GENE + gc)     = o0;
                *(float4*)(outf + gr * D_GENE + gc + 4) = o1;
            }
            __syncwarp();
        }
    }
}

// ---------------- launch ----------------
extern "C" void kernel_launch(void* const* d_in, const int* in_sizes, int n_in,
                              void* d_out, int out_size) {
    const float* expr = (const float*)d_in[0];
    const float* enc  = (const float*)d_in[1];
    const float* pd   = (const float*)d_in[2];
    const float* T    = (const float*)d_in[3];
    const float* gr   = (const float*)d_in[4];
    float* out = (float*)d_out;

    // Order chosen so the 4th launch (ncu capture slot) is the dominant GEMM1.
    k_cvt_enc<<<(N_CELLS * D_EMB) / 256, 256>>>(enc);
    k_cvt_T<<<(D_EMB * D_EMB) / 256, 256>>>(T);
    gemm_wmma7<0><<<dim3(D_EMB / 128,  N_CELLS / 128), 128>>>(nullptr, nullptr);
    gemm_wmma7<1><<<dim3(N_CELLS / 128, N_CELLS / 128), 128>>>(pd, nullptr);
    k_cvt_expr<<<(N_CELLS * D_GENE) / 256, 256>>>(expr);
    k_cvt_gr<<<(D_GENE * D_GENE) / 256, 256>>>(gr);
    gemm_wmma7<2><<<dim3(D_GENE / 128, N_CELLS / 128), 128>>>(nullptr, nullptr);
    gemm_wmma7<3><<<dim3(D_GENE / 128, N_CELLS / 128), 128>>>(nullptr, out);
}